// round 3
// baseline (speedup 1.0000x reference)
#include <cuda_runtime.h>
#include <math.h>

#define NN 512
#define FF 64
#define SS 5
#define TT 32
#define NC 4      // sender chunks per receiver
#define TSZ 16    // sender tile size

// -------- device scratch (no allocations allowed) --------
__device__ float g_nf0[NN*FF];          // node feats channel 0
__device__ float g_nf1[NN*3*FF];        // node feats channels 1:4, layout [n][m][f]
__device__ float g_x0[NN*FF];           // linear-transformed ch0
__device__ float g_x1[NN*3*FF];         // linear-transformed ch1:4
__device__ float g_Apart[NC*NN*9*FF];   // partial segment sums
__device__ float g_pos[NN*3];           // current positions

// packed f32x2 FMA (SASS FFMA2) — ptxas never auto-fuses this from C++
__device__ __forceinline__ unsigned long long ffma2(unsigned long long a,
                                                    unsigned long long b,
                                                    unsigned long long c) {
    unsigned long long d;
    asm("fma.rn.f32x2 %0, %1, %2, %3;" : "=l"(d) : "l"(a), "l"(b), "l"(c));
    return d;
}
__device__ __forceinline__ unsigned long long pack2(float a, float b) {
    unsigned long long r;
    asm("mov.b64 %0, {%1, %2};" : "=l"(r) : "f"(a), "f"(b));
    return r;
}
__device__ __forceinline__ float hsum2(unsigned long long p) {
    float lo = __uint_as_float((unsigned)(p & 0xffffffffULL));
    float hi = __uint_as_float((unsigned)(p >> 32));
    return lo + hi;
}

// -------- embed: h = onehot@W + te@W + b ; also reset pos --------
__global__ void k_embed(const float* __restrict__ pos_in, const int* __restrict__ nodef,
                        const float* __restrict__ te, const float* __restrict__ W_embed,
                        const float* __restrict__ b_embed) {
    int n = blockIdx.x, f = threadIdx.x;
    if (f < 3) g_pos[n*3+f] = pos_in[n*3+f];
    int sp = nodef[n] - 1;
    float h = W_embed[sp*FF + f] + b_embed[f];
    #pragma unroll
    for (int t = 0; t < TT; t++) h = fmaf(te[t], W_embed[(SS+t)*FF + f], h);
    g_nf0[n*FF + f] = h;
}

// -------- per-layer node linear: x0 = nf0 @ Wl0 ; x1 = nf1 @ Wl1 --------
template<bool FIRST>
__global__ void k_linear(const float* __restrict__ Wlin) {
    __shared__ float s0[FF];
    __shared__ float s1[3][FF];
    int n = blockIdx.x, f = threadIdx.x;
    s0[f] = g_nf0[n*FF + f];
    if (!FIRST) {
        s1[0][f] = g_nf1[(n*3+0)*FF + f];
        s1[1][f] = g_nf1[(n*3+1)*FF + f];
        s1[2][f] = g_nf1[(n*3+2)*FF + f];
    }
    __syncthreads();
    float a0 = 0.f, a1x = 0.f, a1y = 0.f, a1z = 0.f;
    #pragma unroll 8
    for (int g = 0; g < FF; g++) {
        float w0 = Wlin[g*FF + f];
        a0 = fmaf(s0[g], w0, a0);
        if (!FIRST) {
            float w1 = Wlin[FF*FF + g*FF + f];
            a1x = fmaf(s1[0][g], w1, a1x);
            a1y = fmaf(s1[1][g], w1, a1y);
            a1z = fmaf(s1[2][g], w1, a1z);
        }
    }
    g_x0[n*FF + f] = a0;
    if (!FIRST) {
        g_x1[(n*3+0)*FF + f] = a1x;
        g_x1[(n*3+1)*FF + f] = a1y;
        g_x1[(n*3+2)*FF + f] = a1z;
    }
}

// -------- edge kernel: per (receiver, chunk), accumulate A partials --------
// NJ = 3 for layer 0 (s1 == 0), NJ = 5 for layer 1. w[...,5] column is never needed.
template<int NJ>
__global__ void __launch_bounds__(64) k_edge(const float* __restrict__ We1,
                                             const float* __restrict__ be1,
                                             const float* __restrict__ We2) {
    const int c = blockIdx.x, r = blockIdx.y, f = threadIdx.x;
    __shared__ float sWe1[32], sBe1[32];
    __shared__ float sY1[TSZ][3];
    __shared__ float sY2[TSZ][5];
    __shared__ float sRl[TSZ];
    __shared__ float sVal[TSZ];
    __shared__ __align__(16) float sHe[TSZ][32];

    if (f < 32) { sWe1[f] = We1[f]; sBe1[f] = be1[f]; }
    const float prx = g_pos[r*3+0], pry = g_pos[r*3+1], prz = g_pos[r*3+2];

    // W_e2 columns for this f, packed in pairs along k (NJ*16 x 64-bit regs)
    unsigned long long w2p[NJ][16];
    #pragma unroll
    for (int k2 = 0; k2 < 16; k2++)
        #pragma unroll
        for (int j = 0; j < NJ; j++)
            w2p[j][k2] = pack2(We2[(2*k2)*384 + f*6 + j],
                               We2[(2*k2+1)*384 + f*6 + j]);

    float acc[9];
    #pragma unroll
    for (int ch = 0; ch < 9; ch++) acc[ch] = 0.f;

    const int base = c * (NN/NC);
    for (int tile = 0; tile < (NN/NC)/TSZ; tile++) {
        __syncthreads();
        if (f < TSZ) {
            int s = base + tile*TSZ + f;
            float vx = prx - g_pos[s*3+0];
            float vy = pry - g_pos[s*3+1];
            float vz = prz - g_pos[s*3+2];
            float r2 = vx*vx + vy*vy + vz*vz;
            float rl = sqrtf(r2);
            int ok = (s != r);
            float inv = ok ? (1.0f/rl) : 0.0f;
            float ux = vx*inv, uy = vy*inv, uz = vz*inv;
            sRl[f] = rl;
            sVal[f] = ok ? 1.0f : 0.0f;
            const float s3  = 1.7320508075688772f;
            const float s5h = 0.5f * 2.2360679774997896f;
            const float s15 = 3.8729833462074170f;
            const float s15h = 0.5f * 3.8729833462074170f;
            sY1[f][0] = s3*ux; sY1[f][1] = s3*uy; sY1[f][2] = s3*uz;
            sY2[f][0] = s15*ux*uy;
            sY2[f][1] = s15*uy*uz;
            sY2[f][2] = s5h*(3.f*uz*uz - 1.f);
            sY2[f][3] = s15*ux*uz;
            sY2[f][4] = s15h*(ux*ux - uy*uy);
        }
        __syncthreads();
        // he = silu(r * We1 + be1), zeroed for the s==r slot (kills all its terms)
        #pragma unroll
        for (int i = 0; i < (TSZ*32)/64; i++) {
            int idx = i*64 + f; int sl = idx >> 5, k = idx & 31;
            float x = fmaf(sRl[sl], sWe1[k], sBe1[k]);
            sHe[sl][k] = (x / (1.0f + expf(-x))) * sVal[sl];
        }
        __syncthreads();
        #pragma unroll 1
        for (int sl = 0; sl < TSZ; sl++) {
            int s = base + tile*TSZ + sl;
            float a0v = g_x0[s*FF + f];
            float a1x = 0.f, a1y = 0.f, a1z = 0.f;
            if (NJ > 3) {
                a1x = g_x1[(s*3+0)*FF + f];
                a1y = g_x1[(s*3+1)*FF + f];
                a1z = g_x1[(s*3+2)*FF + f];
            }
            // packed dot products: wj[j] = sum_k he[k] * We2[k, f*6+j]
            const unsigned long long* he2 =
                reinterpret_cast<const unsigned long long*>(&sHe[sl][0]);
            unsigned long long wp[NJ];
            #pragma unroll
            for (int j = 0; j < NJ; j++) wp[j] = 0ULL;
            #pragma unroll
            for (int k2 = 0; k2 < 16; k2++) {
                unsigned long long h = he2[k2];
                #pragma unroll
                for (int j = 0; j < NJ; j++) wp[j] = ffma2(h, w2p[j][k2], wp[j]);
            }
            float wj[NJ];
            #pragma unroll
            for (int j = 0; j < NJ; j++) wj[j] = hsum2(wp[j]);

            float Y1x = sY1[sl][0], Y1y = sY1[sl][1], Y1z = sY1[sl][2];
            acc[0] = fmaf(wj[0], a0v, acc[0]);
            float w1a = wj[1] * a0v;
            acc[1] = fmaf(w1a, Y1x, acc[1]);
            acc[2] = fmaf(w1a, Y1y, acc[2]);
            acc[3] = fmaf(w1a, Y1z, acc[3]);
            float w2a = wj[2] * a0v;
            acc[4] = fmaf(w2a, sY2[sl][0], acc[4]);
            acc[5] = fmaf(w2a, sY2[sl][1], acc[5]);
            acc[6] = fmaf(w2a, sY2[sl][2], acc[6]);
            acc[7] = fmaf(w2a, sY2[sl][3], acc[7]);
            acc[8] = fmaf(w2a, sY2[sl][4], acc[8]);
            if (NJ > 3) {
                float d1 = a1x*Y1x + a1y*Y1y + a1z*Y1z;
                acc[0] = fmaf(wj[3], d1, acc[0]);
                float crx = a1y*Y1z - a1z*Y1y;
                float cry = a1z*Y1x - a1x*Y1z;
                float crz = a1x*Y1y - a1y*Y1x;
                acc[1] = fmaf(wj[4], crx, acc[1]);
                acc[2] = fmaf(wj[4], cry, acc[2]);
                acc[3] = fmaf(wj[4], crz, acc[3]);
            }
        }
    }
    #pragma unroll
    for (int ch = 0; ch < 9; ch++)
        g_Apart[((c*NN + r)*9 + ch)*FF + f] = acc[ch];
}

// -------- node update: reduce partials, nonlinearity, readout, pos += --------
__global__ void k_node(const int* __restrict__ nodef,
                       const float* __restrict__ Wp0, const float* __restrict__ Wp1,
                       const float* __restrict__ Wr1, const float* __restrict__ br1,
                       const float* __restrict__ Wr2g) {
    int n = blockIdx.x, f = threadIdx.x;
    float A[9];
    #pragma unroll
    for (int ch = 0; ch < 9; ch++) {
        float s = 0.f;
        #pragma unroll
        for (int c = 0; c < NC; c++) s += g_Apart[((c*NN + n)*9 + ch)*FF + f];
        A[ch] = s / 511.0f;
    }
    float A0 = A[0];
    float n1 = A[1]*A[1] + A[2]*A[2] + A[3]*A[3];
    float n2 = A[4]*A[4] + A[5]*A[5] + A[6]*A[6] + A[7]*A[7] + A[8]*A[8];
    int sp = nodef[n] - 1;
    const float* w0 = Wp0 + (sp*FF + f)*6;
    float A02 = A0*A0;
    float out0 = w0[0]*A0 + w0[1]*A02 + w0[2]*A02*A0 + w0[3]*n1 + w0[4]*n2 + w0[5]*A0*n1;
    const float* w1 = Wp1 + (sp*FF + f)*3;
    float gp = w1[0] + w1[1]*A0 + w1[2]*A02;
    float o1x = gp*A[1], o1y = gp*A[2], o1z = gp*A[3];
    g_nf0[n*FF + f] = out0;
    g_nf1[(n*3+0)*FF + f] = o1x;
    g_nf1[(n*3+1)*FF + f] = o1y;
    g_nf1[(n*3+2)*FF + f] = o1z;

    __shared__ float sO[FF];
    sO[f] = out0;
    __syncthreads();
    float hx = br1[f];
    #pragma unroll 8
    for (int g = 0; g < FF; g++) hx = fmaf(sO[g], Wr1[g*FF + f], hx);
    float hr = hx / (1.0f + expf(-hx));
    __shared__ float sH[FF];
    sH[f] = hr;
    __syncthreads();
    float gate = 0.f;
    #pragma unroll 8
    for (int m = 0; m < FF; m++) gate = fmaf(sH[m], Wr2g[m*FF + f], gate);

    __shared__ float sRed[3][FF];
    sRed[0][f] = gate*o1x; sRed[1][f] = gate*o1y; sRed[2][f] = gate*o1z;
    __syncthreads();
    if (f < 3) {
        float v = 0.f;
        for (int g = 0; g < FF; g++) v += sRed[f][g];
        g_pos[n*3 + f] += v;   // deterministic: one thread per component
    }
}

__global__ void k_out(const float* __restrict__ pos_in, float* __restrict__ out) {
    int i = blockIdx.x*blockDim.x + threadIdx.x;
    if (i < NN*3) out[i] = g_pos[i] - pos_in[i];
}

extern "C" void kernel_launch(void* const* d_in, const int* in_sizes, int n_in,
                              void* d_out, int out_size) {
    const float* positions = (const float*)d_in[0];
    const int*   nodef     = (const int*)  d_in[1];
    const float* te        = (const float*)d_in[2];
    // d_in[3]/[4] = senders/receivers: graph is fully connected, structure used directly
    const float* W_embed   = (const float*)d_in[5];
    const float* b_embed   = (const float*)d_in[6];
    const float* W_lin     = (const float*)d_in[7];
    const float* W_e1      = (const float*)d_in[8];
    const float* b_e1      = (const float*)d_in[9];
    const float* W_e2      = (const float*)d_in[10];
    const float* Wp0       = (const float*)d_in[11];
    const float* Wp1       = (const float*)d_in[12];
    const float* Wr1       = (const float*)d_in[13];
    const float* br1       = (const float*)d_in[14];
    // d_in[15] = Wr2s: unused by the reference
    const float* Wr2g      = (const float*)d_in[16];
    float* out = (float*)d_out;

    k_embed<<<NN, FF>>>(positions, nodef, te, W_embed, b_embed);

    // layer 0 (s1 == 0 -> only j in {0,1,2})
    k_linear<true><<<NN, FF>>>(W_lin);
    k_edge<3><<<dim3(NC, NN), 64>>>(W_e1, b_e1, W_e2);
    k_node<<<NN, FF>>>(nodef, Wp0, Wp1, Wr1, br1, Wr2g);

    // layer 1 (full: j in {0..4}; j==5 multiplies an identically-zero term)
    k_linear<false><<<NN, FF>>>(W_lin + 3*FF*FF);
    k_edge<5><<<dim3(NC, NN), 64>>>(W_e1 + 32, b_e1 + 32, W_e2 + 32*384);
    k_node<<<NN, FF>>>(nodef, Wp0 + SS*FF*6, Wp1 + SS*FF*3, Wr1 + FF*FF, br1 + FF, Wr2g + FF*FF);

    k_out<<<(NN*3 + 255)/256, 256>>>(positions, out);
}

// round 4
// speedup vs baseline: 1.0087x; 1.0087x over previous
#include <cuda_runtime.h>
#include <math.h>

#define NN 512
#define FF 64
#define SS 5
#define TT 32
#define NC 4      // sender chunks per receiver
#define TSZ 16    // sender tile size

// -------- device scratch (no allocations allowed) --------
__device__ float g_nf0[NN*FF];          // node feats channel 0
__device__ float g_nf1[NN*3*FF];        // node feats channels 1:4, layout [n][m][f]
__device__ float g_x0[NN*FF];           // linear-transformed ch0
__device__ float g_x1[NN*3*FF];         // linear-transformed ch1:4
__device__ float g_Apart[NC*NN*9*FF];   // partial segment sums
__device__ float g_pos[NN*3];           // current positions

// packed f32x2 FMA (SASS FFMA2) — ptxas never auto-fuses this from C++
__device__ __forceinline__ unsigned long long ffma2(unsigned long long a,
                                                    unsigned long long b,
                                                    unsigned long long c) {
    unsigned long long d;
    asm("fma.rn.f32x2 %0, %1, %2, %3;" : "=l"(d) : "l"(a), "l"(b), "l"(c));
    return d;
}
__device__ __forceinline__ unsigned long long pack2(float a, float b) {
    unsigned long long r;
    asm("mov.b64 %0, {%1, %2};" : "=l"(r) : "f"(a), "f"(b));
    return r;
}
__device__ __forceinline__ float hsum2(unsigned long long p) {
    float lo = __uint_as_float((unsigned)(p & 0xffffffffULL));
    float hi = __uint_as_float((unsigned)(p >> 32));
    return lo + hi;
}

// -------- embed: h = onehot@W + te@W + b ; also reset pos --------
__global__ void k_embed(const float* __restrict__ pos_in, const int* __restrict__ nodef,
                        const float* __restrict__ te, const float* __restrict__ W_embed,
                        const float* __restrict__ b_embed) {
    int n = blockIdx.x, f = threadIdx.x;
    if (f < 3) g_pos[n*3+f] = pos_in[n*3+f];
    int sp = nodef[n] - 1;
    float h = W_embed[sp*FF + f] + b_embed[f];
    #pragma unroll
    for (int t = 0; t < TT; t++) h = fmaf(te[t], W_embed[(SS+t)*FF + f], h);
    g_nf0[n*FF + f] = h;
}

// -------- per-layer node linear: x0 = nf0 @ Wl0 ; x1 = nf1 @ Wl1 --------
template<bool FIRST>
__global__ void k_linear(const float* __restrict__ Wlin) {
    __shared__ float s0[FF];
    __shared__ float s1[3][FF];
    int n = blockIdx.x, f = threadIdx.x;
    s0[f] = g_nf0[n*FF + f];
    if (!FIRST) {
        s1[0][f] = g_nf1[(n*3+0)*FF + f];
        s1[1][f] = g_nf1[(n*3+1)*FF + f];
        s1[2][f] = g_nf1[(n*3+2)*FF + f];
    }
    __syncthreads();
    float a0 = 0.f, a1x = 0.f, a1y = 0.f, a1z = 0.f;
    #pragma unroll 8
    for (int g = 0; g < FF; g++) {
        float w0 = Wlin[g*FF + f];
        a0 = fmaf(s0[g], w0, a0);
        if (!FIRST) {
            float w1 = Wlin[FF*FF + g*FF + f];
            a1x = fmaf(s1[0][g], w1, a1x);
            a1y = fmaf(s1[1][g], w1, a1y);
            a1z = fmaf(s1[2][g], w1, a1z);
        }
    }
    g_x0[n*FF + f] = a0;
    if (!FIRST) {
        g_x1[(n*3+0)*FF + f] = a1x;
        g_x1[(n*3+1)*FF + f] = a1y;
        g_x1[(n*3+2)*FF + f] = a1z;
    }
}

// -------- edge kernel: per (receiver, chunk), accumulate A partials --------
// NJ = 3 for layer 0 (s1 == 0), NJ = 5 for layer 1. w[...,5] column is never needed.
template<int NJ>
__global__ void __launch_bounds__(64) k_edge(const float* __restrict__ We1,
                                             const float* __restrict__ be1,
                                             const float* __restrict__ We2) {
    const int c = blockIdx.x, r = blockIdx.y, f = threadIdx.x;
    __shared__ float sWe1[32], sBe1[32];
    __shared__ float sY1[TSZ][3];
    __shared__ float sY2[TSZ][5];
    __shared__ float sRl[TSZ];
    __shared__ float sVal[TSZ];
    __shared__ __align__(16) float sHe[TSZ][32];

    if (f < 32) { sWe1[f] = We1[f]; sBe1[f] = be1[f]; }
    const float prx = g_pos[r*3+0], pry = g_pos[r*3+1], prz = g_pos[r*3+2];

    // W_e2 columns for this f, packed in pairs along k (NJ*16 x 64-bit regs)
    unsigned long long w2p[NJ][16];
    #pragma unroll
    for (int k2 = 0; k2 < 16; k2++)
        #pragma unroll
        for (int j = 0; j < NJ; j++)
            w2p[j][k2] = pack2(We2[(2*k2)*384 + f*6 + j],
                               We2[(2*k2+1)*384 + f*6 + j]);

    float acc[9];
    #pragma unroll
    for (int ch = 0; ch < 9; ch++) acc[ch] = 0.f;

    const int base = c * (NN/NC);
    for (int tile = 0; tile < (NN/NC)/TSZ; tile++) {
        __syncthreads();
        if (f < TSZ) {
            int s = base + tile*TSZ + f;
            float vx = prx - g_pos[s*3+0];
            float vy = pry - g_pos[s*3+1];
            float vz = prz - g_pos[s*3+2];
            float r2 = vx*vx + vy*vy + vz*vz;
            float rl = sqrtf(r2);
            int ok = (s != r);
            float inv = ok ? (1.0f/rl) : 0.0f;
            float ux = vx*inv, uy = vy*inv, uz = vz*inv;
            sRl[f] = rl;
            sVal[f] = ok ? 1.0f : 0.0f;
            const float s3  = 1.7320508075688772f;
            const float s5h = 0.5f * 2.2360679774997896f;
            const float s15 = 3.8729833462074170f;
            const float s15h = 0.5f * 3.8729833462074170f;
            sY1[f][0] = s3*ux; sY1[f][1] = s3*uy; sY1[f][2] = s3*uz;
            sY2[f][0] = s15*ux*uy;
            sY2[f][1] = s15*uy*uz;
            sY2[f][2] = s5h*(3.f*uz*uz - 1.f);
            sY2[f][3] = s15*ux*uz;
            sY2[f][4] = s15h*(ux*ux - uy*uy);
        }
        __syncthreads();
        // he = silu(r * We1 + be1), zeroed for the s==r slot (kills all its terms)
        #pragma unroll
        for (int i = 0; i < (TSZ*32)/64; i++) {
            int idx = i*64 + f; int sl = idx >> 5, k = idx & 31;
            float x = fmaf(sRl[sl], sWe1[k], sBe1[k]);
            sHe[sl][k] = (x / (1.0f + expf(-x))) * sVal[sl];
        }
        __syncthreads();
        #pragma unroll 1
        for (int sl = 0; sl < TSZ; sl++) {
            int s = base + tile*TSZ + sl;
            float a0v = g_x0[s*FF + f];
            float a1x = 0.f, a1y = 0.f, a1z = 0.f;
            if (NJ > 3) {
                a1x = g_x1[(s*3+0)*FF + f];
                a1y = g_x1[(s*3+1)*FF + f];
                a1z = g_x1[(s*3+2)*FF + f];
            }
            // packed dot products: wj[j] = sum_k he[k] * We2[k, f*6+j]
            const unsigned long long* he2 =
                reinterpret_cast<const unsigned long long*>(&sHe[sl][0]);
            unsigned long long wp[NJ];
            #pragma unroll
            for (int j = 0; j < NJ; j++) wp[j] = 0ULL;
            #pragma unroll
            for (int k2 = 0; k2 < 16; k2++) {
                unsigned long long h = he2[k2];
                #pragma unroll
                for (int j = 0; j < NJ; j++) wp[j] = ffma2(h, w2p[j][k2], wp[j]);
            }
            float wj[NJ];
            #pragma unroll
            for (int j = 0; j < NJ; j++) wj[j] = hsum2(wp[j]);

            float Y1x = sY1[sl][0], Y1y = sY1[sl][1], Y1z = sY1[sl][2];
            acc[0] = fmaf(wj[0], a0v, acc[0]);
            float w1a = wj[1] * a0v;
            acc[1] = fmaf(w1a, Y1x, acc[1]);
            acc[2] = fmaf(w1a, Y1y, acc[2]);
            acc[3] = fmaf(w1a, Y1z, acc[3]);
            float w2a = wj[2] * a0v;
            acc[4] = fmaf(w2a, sY2[sl][0], acc[4]);
            acc[5] = fmaf(w2a, sY2[sl][1], acc[5]);
            acc[6] = fmaf(w2a, sY2[sl][2], acc[6]);
            acc[7] = fmaf(w2a, sY2[sl][3], acc[7]);
            acc[8] = fmaf(w2a, sY2[sl][4], acc[8]);
            if (NJ > 3) {
                float d1 = a1x*Y1x + a1y*Y1y + a1z*Y1z;
                acc[0] = fmaf(wj[3], d1, acc[0]);
                float crx = a1y*Y1z - a1z*Y1y;
                float cry = a1z*Y1x - a1x*Y1z;
                float crz = a1x*Y1y - a1y*Y1x;
                acc[1] = fmaf(wj[4], crx, acc[1]);
                acc[2] = fmaf(wj[4], cry, acc[2]);
                acc[3] = fmaf(wj[4], crz, acc[3]);
            }
        }
    }
    #pragma unroll
    for (int ch = 0; ch < 9; ch++)
        g_Apart[((c*NN + r)*9 + ch)*FF + f] = acc[ch];
}

// -------- node update: reduce partials, nonlinearity, readout, pos += --------
__global__ void k_node(const int* __restrict__ nodef,
                       const float* __restrict__ Wp0, const float* __restrict__ Wp1,
                       const float* __restrict__ Wr1, const float* __restrict__ br1,
                       const float* __restrict__ Wr2g) {
    int n = blockIdx.x, f = threadIdx.x;
    float A[9];
    #pragma unroll
    for (int ch = 0; ch < 9; ch++) {
        float s = 0.f;
        #pragma unroll
        for (int c = 0; c < NC; c++) s += g_Apart[((c*NN + n)*9 + ch)*FF + f];
        A[ch] = s / 511.0f;
    }
    float A0 = A[0];
    float n1 = A[1]*A[1] + A[2]*A[2] + A[3]*A[3];
    float n2 = A[4]*A[4] + A[5]*A[5] + A[6]*A[6] + A[7]*A[7] + A[8]*A[8];
    int sp = nodef[n] - 1;
    const float* w0 = Wp0 + (sp*FF + f)*6;
    float A02 = A0*A0;
    float out0 = w0[0]*A0 + w0[1]*A02 + w0[2]*A02*A0 + w0[3]*n1 + w0[4]*n2 + w0[5]*A0*n1;
    const float* w1 = Wp1 + (sp*FF + f)*3;
    float gp = w1[0] + w1[1]*A0 + w1[2]*A02;
    float o1x = gp*A[1], o1y = gp*A[2], o1z = gp*A[3];
    g_nf0[n*FF + f] = out0;
    g_nf1[(n*3+0)*FF + f] = o1x;
    g_nf1[(n*3+1)*FF + f] = o1y;
    g_nf1[(n*3+2)*FF + f] = o1z;

    __shared__ float sO[FF];
    sO[f] = out0;
    __syncthreads();
    float hx = br1[f];
    #pragma unroll 8
    for (int g = 0; g < FF; g++) hx = fmaf(sO[g], Wr1[g*FF + f], hx);
    float hr = hx / (1.0f + expf(-hx));
    __shared__ float sH[FF];
    sH[f] = hr;
    __syncthreads();
    float gate = 0.f;
    #pragma unroll 8
    for (int m = 0; m < FF; m++) gate = fmaf(sH[m], Wr2g[m*FF + f], gate);

    __shared__ float sRed[3][FF];
    sRed[0][f] = gate*o1x; sRed[1][f] = gate*o1y; sRed[2][f] = gate*o1z;
    __syncthreads();
    if (f < 3) {
        float v = 0.f;
        for (int g = 0; g < FF; g++) v += sRed[f][g];
        g_pos[n*3 + f] += v;   // deterministic: one thread per component
    }
}

__global__ void k_out(const float* __restrict__ pos_in, float* __restrict__ out) {
    int i = blockIdx.x*blockDim.x + threadIdx.x;
    if (i < NN*3) out[i] = g_pos[i] - pos_in[i];
}

extern "C" void kernel_launch(void* const* d_in, const int* in_sizes, int n_in,
                              void* d_out, int out_size) {
    const float* positions = (const float*)d_in[0];
    const int*   nodef     = (const int*)  d_in[1];
    const float* te        = (const float*)d_in[2];
    // d_in[3]/[4] = senders/receivers: graph is fully connected, structure used directly
    const float* W_embed   = (const float*)d_in[5];
    const float* b_embed   = (const float*)d_in[6];
    const float* W_lin     = (const float*)d_in[7];
    const float* W_e1      = (const float*)d_in[8];
    const float* b_e1      = (const float*)d_in[9];
    const float* W_e2      = (const float*)d_in[10];
    const float* Wp0       = (const float*)d_in[11];
    const float* Wp1       = (const float*)d_in[12];
    const float* Wr1       = (const float*)d_in[13];
    const float* br1       = (const float*)d_in[14];
    // d_in[15] = Wr2s: unused by the reference
    const float* Wr2g      = (const float*)d_in[16];
    float* out = (float*)d_out;

    k_embed<<<NN, FF>>>(positions, nodef, te, W_embed, b_embed);

    // layer 0 (s1 == 0 -> only j in {0,1,2})
    k_linear<true><<<NN, FF>>>(W_lin);
    k_edge<3><<<dim3(NC, NN), 64>>>(W_e1, b_e1, W_e2);
    k_node<<<NN, FF>>>(nodef, Wp0, Wp1, Wr1, br1, Wr2g);

    // layer 1 (full: j in {0..4}; j==5 multiplies an identically-zero term)
    k_linear<false><<<NN, FF>>>(W_lin + 3*FF*FF);
    k_edge<5><<<dim3(NC, NN), 64>>>(W_e1 + 32, b_e1 + 32, W_e2 + 32*384);
    k_node<<<NN, FF>>>(nodef, Wp0 + SS*FF*6, Wp1 + SS*FF*3, Wr1 + FF*FF, br1 + FF, Wr2g + FF*FF);

    k_out<<<(NN*3 + 255)/256, 256>>>(positions, out);
}